// round 4
// baseline (speedup 1.0000x reference)
#include <cuda_runtime.h>
#include <math_constants.h>

// Problem shape (fixed by setup_inputs)
#define BB 2
#define NN 8192
#define MM 8192
#define FF 128
#define KK 3
#define KEEP 4               // per-split candidates kept
#define SPLITS 8
#define TILE (NN / SPLITS)   // 1024 candidates per split
#define BLK1 128             // targets per block in scan kernel

// Scratch (no cudaMalloc allowed)
__device__ float4 g_pc4[BB * NN];                   // (x, y, z, s2) ref-rounded
__device__ float2 g_cand[BB * MM * SPLITS * KEEP];  // (d2, idx-as-float)

// Reference-matching sum of squares: ((x*x + y*y) + z*z), all ops rn, no fma
__device__ __forceinline__ float sumsq_ref(float x, float y, float z) {
    return __fadd_rn(__fadd_rn(__fmul_rn(x, x), __fmul_rn(y, y)), __fmul_rn(z, z));
}

// ---------------------------------------------------------------------------
// Kernel 0: pack source points into float4 with ref-rounded |p|^2
// ---------------------------------------------------------------------------
__global__ void prep_kernel(const float* __restrict__ spc) {
    int t = blockIdx.x * blockDim.x + threadIdx.x;
    if (t < BB * NN) {
        float x = spc[3 * t + 0];
        float y = spc[3 * t + 1];
        float z = spc[3 * t + 2];
        g_pc4[t] = make_float4(x, y, z, sumsq_ref(x, y, z));
    }
}

// ---------------------------------------------------------------------------
// Kernel 1: brute-force scan, per-thread top-4 (min d2) over one N-split.
// XLA strength-reduces the K=3 einsum to multiply+reduce (NO fma):
//   cross = ((x*tx + y*ty) + z*tz), every op separately rounded.
// d2 = (t2 + s2) - 2*cross with explicit rn ops. Strict < keeps lowest index.
// ---------------------------------------------------------------------------
__global__ void __launch_bounds__(BLK1) knn_scan(const float* __restrict__ tpc) {
    __shared__ float4 tile[TILE];

    const int b     = blockIdx.z;
    const int split = blockIdx.y;
    const int m     = blockIdx.x * BLK1 + threadIdx.x;
    const int nbase = split * TILE;

    const float4* __restrict__ src = g_pc4 + b * NN + nbase;
    for (int i = threadIdx.x; i < TILE; i += BLK1) tile[i] = src[i];

    const float* tp = tpc + (size_t)(b * MM + m) * 3;
    const float tx = tp[0], ty = tp[1], tz = tp[2];
    const float t2 = sumsq_ref(tx, ty, tz);

    __syncthreads();

    float b0 = CUDART_INF_F, b1 = CUDART_INF_F, b2 = CUDART_INF_F, b3 = CUDART_INF_F;
    int   i0 = 0, i1 = 0, i2 = 0, i3 = 0;

#pragma unroll 8
    for (int i = 0; i < TILE; ++i) {
        float4 p = tile[i];  // warp-uniform -> smem broadcast
        // cross: mul + pairwise add, ascending dim, all rn, NO fma
        float mx = __fmul_rn(p.x, tx);
        float my = __fmul_rn(p.y, ty);
        float mz = __fmul_rn(p.z, tz);
        float c  = __fadd_rn(__fadd_rn(mx, my), mz);
        // d2 = (t2 + s2) - 2*c ; 2*c == c+c exactly
        float d2 = __fsub_rn(__fadd_rn(t2, p.w), __fadd_rn(c, c));
        if (d2 < b3) {
            if (d2 < b1) {
                if (d2 < b0) { b3=b2; i3=i2; b2=b1; i2=i1; b1=b0; i1=i0; b0=d2; i0=i; }
                else         { b3=b2; i3=i2; b2=b1; i2=i1; b1=d2; i1=i; }
            } else {
                if (d2 < b2) { b3=b2; i3=i2; b2=d2; i2=i; }
                else         { b3=d2; i3=i; }
            }
        }
    }

    float2* out = g_cand + ((size_t)(b * MM + m) * SPLITS + split) * KEEP;
    out[0] = make_float2(b0, __int_as_float(nbase + i0));
    out[1] = make_float2(b1, __int_as_float(nbase + i1));
    out[2] = make_float2(b2, __int_as_float(nbase + i2));
    out[3] = make_float2(b3, __int_as_float(nbase + i3));
}

// ---------------------------------------------------------------------------
// Kernel 2: merge 8x4 candidates with the reference key
//   d = sqrt(max(d2,0)) fp32, tie -> lower index (stable top_k),
// then ref-rounded weights + warp-wide float4 feature blend.
// ---------------------------------------------------------------------------
__device__ __forceinline__ bool key_lt(float dA, int iA, float dB, int iB) {
    return (dA < dB) || (dA == dB && iA < iB);
}

__global__ void __launch_bounds__(256) merge_gather(const float* __restrict__ sfeat,
                                                    float* __restrict__ out) {
    const int gwarp = (blockIdx.x * blockDim.x + threadIdx.x) >> 5;
    const int lane  = threadIdx.x & 31;
    const int b     = gwarp / MM;
    const int m     = gwarp % MM;

    const float2* __restrict__ cand = g_cand + (size_t)(b * MM + m) * SPLITS * KEEP;

    float d0 = CUDART_INF_F, d1 = CUDART_INF_F, d2 = CUDART_INF_F;
    int   i0 = 0x7FFFFFFF,  i1 = 0x7FFFFFFF,  i2 = 0x7FFFFFFF;

#pragma unroll
    for (int j = 0; j < SPLITS * KEEP; ++j) {
        float2 c  = cand[j];  // warp-uniform broadcast
        float  dd = __fsqrt_rn(fmaxf(c.x, 0.0f));   // reference key (fp32 dist)
        int    ix = __float_as_int(c.y);
        if (key_lt(dd, ix, d2, i2)) {
            if (key_lt(dd, ix, d0, i0))      { d2=d1; i2=i1; d1=d0; i1=i0; d0=dd; i0=ix; }
            else if (key_lt(dd, ix, d1, i1)) { d2=d1; i2=i1; d1=dd; i1=ix; }
            else                             { d2=dd; i2=ix; }
        }
    }

    // w = 1/(d + 1e-6); weight = w / sum(w), ascending-k order, all rn
    float w0 = __fdiv_rn(1.0f, __fadd_rn(d0, 1e-6f));
    float w1 = __fdiv_rn(1.0f, __fadd_rn(d1, 1e-6f));
    float w2 = __fdiv_rn(1.0f, __fadd_rn(d2, 1e-6f));
    float s  = __fadd_rn(__fadd_rn(w0, w1), w2);
    w0 = __fdiv_rn(w0, s);
    w1 = __fdiv_rn(w1, s);
    w2 = __fdiv_rn(w2, s);

    const float4* __restrict__ r0 = (const float4*)(sfeat + (size_t)(b * NN + i0) * FF);
    const float4* __restrict__ r1 = (const float4*)(sfeat + (size_t)(b * NN + i1) * FF);
    const float4* __restrict__ r2 = (const float4*)(sfeat + (size_t)(b * NN + i2) * FF);

    float4 v0 = r0[lane];
    float4 v1 = r1[lane];
    float4 v2 = r2[lane];

    // sum over K ascending, mul then add, all rn (matches jnp.sum)
    float4 o;
    o.x = __fadd_rn(__fadd_rn(__fmul_rn(v0.x, w0), __fmul_rn(v1.x, w1)), __fmul_rn(v2.x, w2));
    o.y = __fadd_rn(__fadd_rn(__fmul_rn(v0.y, w0), __fmul_rn(v1.y, w1)), __fmul_rn(v2.y, w2));
    o.z = __fadd_rn(__fadd_rn(__fmul_rn(v0.z, w0), __fmul_rn(v1.z, w1)), __fmul_rn(v2.z, w2));
    o.w = __fadd_rn(__fadd_rn(__fmul_rn(v0.w, w0), __fmul_rn(v1.w, w1)), __fmul_rn(v2.w, w2));

    float4* op = (float4*)(out + (size_t)(b * MM + m) * FF);
    op[lane] = o;
}

// ---------------------------------------------------------------------------
extern "C" void kernel_launch(void* const* d_in, const int* in_sizes, int n_in,
                              void* d_out, int out_size) {
    const float* source_pc   = (const float*)d_in[0];
    const float* target_pc   = (const float*)d_in[1];
    const float* source_feat = (const float*)d_in[2];
    float*       out         = (float*)d_out;

    prep_kernel<<<(BB * NN + 255) / 256, 256>>>(source_pc);

    dim3 g1(MM / BLK1, SPLITS, BB);
    knn_scan<<<g1, BLK1>>>(target_pc);

    const int warps = BB * MM;           // 16384
    merge_gather<<<warps / 8, 256>>>(source_feat, out);
}